// round 16
// baseline (speedup 1.0000x reference)
#include <cuda_runtime.h>

#define Bsz 64
#define Ssz 512
#define Hsz 512
#define Isz 512

typedef unsigned long long u64;

// Scratch (allocation-free rule: __device__ globals)
__device__ float g_xw[134217728];          // [d][s][g][h][b] : 512MB
__device__ float g_h2[2][2][2][Hsz][32];   // [d][buf][bslab][k(=h)][b_l]
__device__ float g_U3[2][Hsz][Hsz][4];     // [d][k][h][g] undup'd, 8MB
__device__ unsigned g_flag[2][2][32];      // [d][bslab][hslab] step flags

__device__ __forceinline__ u64 packf2(float x, float y) {
    u64 r; asm("mov.b64 %0, {%1,%2};" : "=l"(r) : "f"(x), "f"(y)); return r;
}
__device__ __forceinline__ void unpack2(u64 v, float& x, float& y) {
    asm("mov.b64 {%0,%1}, %2;" : "=f"(x), "=f"(y) : "l"(v));
}
__device__ __forceinline__ void fma2(u64& d, u64 a, u64 b) {
    asm("fma.rn.f32x2 %0, %1, %2, %0;" : "+l"(d) : "l"(a), "l"(b));
}
__device__ __forceinline__ void add2(u64& d, u64 a) {
    asm("add.rn.f32x2 %0, %0, %1;" : "+l"(d) : "l"(a));
}
__device__ __forceinline__ float sigm(float x) {
    float e; asm("ex2.approx.f32 %0, %1;" : "=f"(e) : "f"(x * -1.4426950408889634f));
    float r; asm("rcp.approx.f32 %0, %1;" : "=f"(r) : "f"(1.0f + e));
    return r;
}
__device__ __forceinline__ float tanh_(float x) {
    float e; asm("ex2.approx.f32 %0, %1;" : "=f"(e) : "f"(x * 2.8853900817779268f));
    float r; asm("rcp.approx.f32 %0, %1;" : "=f"(r) : "f"(1.0f + e));
    return 1.0f - 2.0f * r;
}
__device__ __forceinline__ void st_release(unsigned* p, unsigned v) {
    asm volatile("st.release.gpu.global.u32 [%0], %1;" :: "l"(p), "r"(v) : "memory");
}
__device__ __forceinline__ unsigned ld_acquire(const unsigned* p) {
    unsigned v;
    asm volatile("ld.acquire.gpu.global.u32 %0, [%1];" : "=r"(v) : "l"(p) : "memory");
    return v;
}
__device__ __forceinline__ void mbar_init(unsigned mbar, unsigned count) {
    asm volatile("mbarrier.init.shared.b64 [%0], %1;" :: "r"(mbar), "r"(count) : "memory");
}
__device__ __forceinline__ void mbar_expect_tx(unsigned mbar, unsigned bytes) {
    asm volatile("mbarrier.arrive.expect_tx.shared.b64 _, [%0], %1;"
                 :: "r"(mbar), "r"(bytes) : "memory");
}
__device__ __forceinline__ void bulk_g2s(unsigned dst, const void* src,
                                         unsigned bytes, unsigned mbar) {
    asm volatile(
        "cp.async.bulk.shared::cluster.global.mbarrier::complete_tx::bytes "
        "[%0], [%1], %2, [%3];"
        :: "r"(dst), "l"(src), "r"(bytes), "r"(mbar) : "memory");
}
__device__ __forceinline__ void mbar_wait(unsigned mbar, unsigned parity) {
    unsigned done;
    do {
        asm volatile(
            "{\n\t.reg .pred p;\n\t"
            "mbarrier.try_wait.parity.acquire.cta.shared::cta.b64 p, [%1], %2;\n\t"
            "selp.b32 %0, 1, 0, p;\n\t}"
            : "=r"(done) : "r"(mbar), "r"(parity) : "memory");
    } while (!done);
}

// ---------------------------------------------------------------------------
__global__ void k_init() {
    int i = blockIdx.x * 256 + threadIdx.x;
    float* ph = &g_h2[0][0][0][0][0];
    if (i < 2 * 2 * 2 * Hsz * 32) ph[i] = 0.0f;
    if (i < 128) (&g_flag[0][0][0])[i] = 0u;
}

// Build g_U3[d][k][h][g] = U[d][g][k][h] (gates contiguous, undup'd).
__global__ void k_u3(const float* __restrict__ Uf, const float* __restrict__ Ub) {
    int i = blockIdx.x * 256 + threadIdx.x;       // over 2*512*512 (d,k,h)
    int d = i >> 18;
    int k = (i >> 9) & 511;
    int h = i & 511;
    const float* U = d ? Ub : Uf;
    float4 v;
    v.x = U[0 * 262144 + k * 512 + h];
    v.y = U[1 * 262144 + k * 512 + h];
    v.z = U[2 * 262144 + k * 512 + h];
    v.w = U[3 * 262144 + k * 512 + h];
    *(float4*)&g_U3[d][k][h][0] = v;
}

// ---------------------------------------------------------------------------
// Input projection: xw[d][s][g][h][b] = sum_i x[b][s][i] * W_d[g][i][h] + b_d[g][h]
__global__ __launch_bounds__(256) void k_xw(
    const float* __restrict__ x,
    const float* __restrict__ Wf, const float* __restrict__ Wb,
    const float* __restrict__ bf, const float* __restrict__ bb)
{
    __shared__ float As[32][66];   // As[k][row(b)]
    __shared__ float Bs[32][68];   // Bs[k][col(h)]

    const int tid = threadIdx.x;
    const int s = blockIdx.y;
    const int ct = blockIdx.x;             // 0..63
    const int d = ct >> 5;
    const int g = (ct >> 3) & 3;
    const int h0 = (ct & 7) * 64;

    const float* W = (d ? Wb : Wf) + (size_t)g * Hsz * Isz + h0;
    const float* bias = (d ? bb : bf) + g * Hsz + h0;

    const int ra = tid >> 3, k4 = tid & 7;     // A staging
    const int c4 = tid & 15, kb = tid >> 4;    // B staging
    const float* xg = x + ((size_t)ra * Ssz + s) * Isz + k4 * 4;
    const size_t xrow2 = (size_t)32 * Ssz * Isz;

    const int l = tid & 31, w = tid >> 5;

    u64 acc[2][4] = {};

    float4 rA0 = *(const float4*)(xg);
    float4 rA1 = *(const float4*)(xg + xrow2);
    float4 rB0 = *(const float4*)(W + (size_t)kb * Hsz + c4 * 4);
    float4 rB1 = *(const float4*)(W + (size_t)(kb + 16) * Hsz + c4 * 4);

    for (int t = 0; t < 16; t++) {
        {
            int kk = k4 * 4;
            As[kk + 0][ra] = rA0.x; As[kk + 1][ra] = rA0.y;
            As[kk + 2][ra] = rA0.z; As[kk + 3][ra] = rA0.w;
            As[kk + 0][ra + 32] = rA1.x; As[kk + 1][ra + 32] = rA1.y;
            As[kk + 2][ra + 32] = rA1.z; As[kk + 3][ra + 32] = rA1.w;
            *(float4*)&Bs[kb][c4 * 4] = rB0;
            *(float4*)&Bs[kb + 16][c4 * 4] = rB1;
        }
        __syncthreads();
        if (t < 15) {
            int k0 = (t + 1) * 32;
            rA0 = *(const float4*)(xg + k0);
            rA1 = *(const float4*)(xg + xrow2 + k0);
            rB0 = *(const float4*)(W + (size_t)(k0 + kb) * Hsz + c4 * 4);
            rB1 = *(const float4*)(W + (size_t)(k0 + kb + 16) * Hsz + c4 * 4);
        }
        #pragma unroll
        for (int kk = 0; kk < 32; kk++) {
            float2 a = *(const float2*)&As[kk][2 * l];
            u64 a0 = packf2(a.x, a.x);
            u64 a1 = packf2(a.y, a.y);
            ulonglong2 b01 = *(const ulonglong2*)&Bs[kk][8 * w];
            ulonglong2 b23 = *(const ulonglong2*)&Bs[kk][8 * w + 4];
            fma2(acc[0][0], a0, b01.x); fma2(acc[0][1], a0, b01.y);
            fma2(acc[0][2], a0, b23.x); fma2(acc[0][3], a0, b23.y);
            fma2(acc[1][0], a1, b01.x); fma2(acc[1][1], a1, b01.y);
            fma2(acc[1][2], a1, b23.x); fma2(acc[1][3], a1, b23.y);
        }
        __syncthreads();
    }

    size_t gb = (((size_t)d * Ssz + s) * 4 + g) * (size_t)Hsz * Bsz;
    #pragma unroll
    for (int j = 0; j < 4; j++) {
        float2 bb2 = *(const float2*)&bias[8 * w + 2 * j];
        float p0, p1, q0, q1;
        unpack2(acc[0][j], p0, p1);
        unpack2(acc[1][j], q0, q1);
        int hc = h0 + 8 * w + 2 * j;
        *(float2*)&g_xw[gb + (size_t)hc * Bsz + 2 * l] =
            make_float2(p0 + bb2.x, q0 + bb2.x);
        *(float2*)&g_xw[gb + (size_t)(hc + 1) * Bsz + 2 * l] =
            make_float2(p1 + bb2.y, q1 + bb2.y);
    }
}

// ---------------------------------------------------------------------------
// Persistent recurrence kernel, per-quarter dependency pipelining.
// Grid 128: d = bx>>6; hslab = (bx&63)>>1 (h0 = 16*hslab); bslab = bx&1.
// 512 threads, 1 block/SM, 4-way split-K (kq = tid>>7).
// Quarter kq depends only on producers hslab in [8kq, 8kq+8): lane t128==0 of
// each quarter polls those 8 flags (MLP), then issues its own 16KB bulk copy
// on its own mbarrier; the quarter's warps wait only on that mbarrier, so
// quarters start as their inputs land instead of after a full-set barrier.
// Smem: mbar 32 | ob 2KB | red 24KB | B 136KB | A 64KB = 231,552 B
#define SM_MB   0
#define SM_OB   32
#define SM_RED  2080
#define SM_BS   26752
#define SM_AS   166016
#define SM_REC  231552

__global__ __launch_bounds__(512, 1) void k_rec(float* __restrict__ out)
{
    extern __shared__ char smraw[];
    float* ob  = (float*)(smraw + SM_OB);    // [32 b][16 h]
    u64*   red = (u64*)  (smraw + SM_RED);   // [3*128][8]
    float* Bsf = (float*)(smraw + SM_BS);    // [k][68]
    float* Ahs = (float*)(smraw + SM_AS);    // [k][32]

    const int tid = threadIdx.x;
    const int kq = tid >> 7;
    const int t128 = tid & 127;
    const int d = blockIdx.x >> 6;
    const int hslab = (blockIdx.x & 63) >> 1;
    const int bslab = blockIdx.x & 1;
    const int h0 = hslab * 16;
    const int b0s = bslab * 32;

    const unsigned smem_u32 = (unsigned)__cvta_generic_to_shared(smraw);
    const unsigned mymb = smem_u32 + SM_MB + kq * 8;
    const unsigned ah_u32 = smem_u32 + SM_AS;

    if (tid == 0) {
        #pragma unroll
        for (int q = 0; q < 4; q++) mbar_init(smem_u32 + SM_MB + q * 8, 1);
    }

    // ---- load U slab once: local (hl,g) -> padded col hq*8+(hq>>2)*4+hp*4+g
    {
        const float* src = &g_U3[d][0][h0][0];
        for (int i = tid; i < 512 * 64; i += 512) {
            int k = i >> 6, j6 = i & 63;
            int hl = j6 >> 2, g = j6 & 3;
            int hqq = hl >> 1, hpp = hl & 1;
            int col = hqq * 8 + (hqq >> 2) * 4 + hpp * 4 + g;
            Bsf[k * 68 + col] = src[(size_t)k * 2048 + j6];
        }
    }

    const int rp = t128 >> 3;                // 0..15
    const int hq = t128 & 7;                 // 0..7
    const int r0 = rp * 2;
    const int bcol = hq * 8 + (hq >> 2) * 4;
    const int kbase = kq * 128;

    unsigned* myflag = &g_flag[d][bslab][hslab];
    const unsigned* flags = &g_flag[d][bslab][0];

    const float* xwd = &g_xw[0] + (size_t)d * Ssz * 4 * Hsz * Bsz;

    float carr[2][2] = {{0.f, 0.f}, {0.f, 0.f}};   // c[row][hp]
    __syncthreads();   // U slab + mbarriers visible

    #pragma unroll 1
    for (int t = 0; t < Ssz; t++) {
        const int s = d ? (Ssz - 1 - t) : t;
        const int buf = t & 1;
        const unsigned parity = (unsigned)(t & 1);

        // seed acc (quarter 0) with xw — issued before waits, overlaps spin
        u64 acc[2][2][2] = {};
        if (kq == 0) {
            #pragma unroll
            for (int hp = 0; hp < 2; hp++) {
                int h = h0 + hq * 2 + hp;
                const float* xp = xwd + (size_t)s * 4 * Hsz * Bsz
                                + (size_t)h * Bsz + b0s + r0;
                float2 vf = *(const float2*)(xp);
                float2 vg = *(const float2*)(xp + (size_t)Hsz * Bsz);
                float2 vi = *(const float2*)(xp + (size_t)2 * Hsz * Bsz);
                float2 vo = *(const float2*)(xp + (size_t)3 * Hsz * Bsz);
                acc[0][hp][0] = packf2(vf.x, vg.x);
                acc[0][hp][1] = packf2(vi.x, vo.x);
                acc[1][hp][0] = packf2(vf.y, vg.y);
                acc[1][hp][1] = packf2(vi.y, vo.y);
            }
        }

        // per-quarter dependency: lane 0 of each quarter polls ONLY its 8
        // producers (MLP poll), then issues this quarter's 16KB bulk copy.
        if (t128 == 0) {
            const unsigned* f8 = flags + kq * 8;
            if (t > 0) {
                for (;;) {
                    unsigned mn = 0xffffffffu;
                    #pragma unroll
                    for (int i = 0; i < 8; i++) {
                        unsigned v = ld_acquire(f8 + i);
                        mn = v < mn ? v : mn;
                    }
                    if (mn >= (unsigned)t) break;
                }
            }
            mbar_expect_tx(mymb, 16384u);
            bulk_g2s(ah_u32 + (unsigned)(kbase * 128),
                     &g_h2[d][buf][bslab][kbase][0], 16384u, mymb);
        }
        mbar_wait(mymb, parity);

        // sync-free GEMM over my 128 k
        #pragma unroll 1
        for (int tt = 0; tt < 8; tt++) {
            const float* Ak = Ahs + (size_t)(kbase + tt * 16) * 32 + r0;
            const float* Bt = Bsf + (size_t)(kbase + tt * 16) * 68 + bcol;
            #pragma unroll
            for (int kk = 0; kk < 16; kk++) {
                float2 a = *(const float2*)(Ak + kk * 32);
                u64 ax = packf2(a.x, a.x);
                u64 ay = packf2(a.y, a.y);
                ulonglong2 b0 = *(const ulonglong2*)(Bt + kk * 68);       // hp=0
                ulonglong2 b1 = *(const ulonglong2*)(Bt + kk * 68 + 4);   // hp=1
                fma2(acc[0][0][0], ax, b0.x);
                fma2(acc[0][0][1], ax, b0.y);
                fma2(acc[0][1][0], ax, b1.x);
                fma2(acc[0][1][1], ax, b1.y);
                fma2(acc[1][0][0], ay, b0.x);
                fma2(acc[1][0][1], ay, b0.y);
                fma2(acc[1][1][0], ay, b1.x);
                fma2(acc[1][1][1], ay, b1.y);
            }
        }

        // quarters 1..3 dump partials
        if (kq > 0) {
            u64* rp_ = red + ((size_t)(kq - 1) * 128 + t128) * 8;
            *(ulonglong2*)(rp_)     = make_ulonglong2(acc[0][0][0], acc[0][0][1]);
            *(ulonglong2*)(rp_ + 2) = make_ulonglong2(acc[0][1][0], acc[0][1][1]);
            *(ulonglong2*)(rp_ + 4) = make_ulonglong2(acc[1][0][0], acc[1][0][1]);
            *(ulonglong2*)(rp_ + 6) = make_ulonglong2(acc[1][1][0], acc[1][1][1]);
        }
        __syncthreads();

        if (kq == 0) {
            #pragma unroll
            for (int q = 0; q < 3; q++) {
                const u64* rp_ = red + ((size_t)q * 128 + t128) * 8;
                add2(acc[0][0][0], rp_[0]); add2(acc[0][0][1], rp_[1]);
                add2(acc[0][1][0], rp_[2]); add2(acc[0][1][1], rp_[3]);
                add2(acc[1][0][0], rp_[4]); add2(acc[1][0][1], rp_[5]);
                add2(acc[1][1][0], rp_[6]); add2(acc[1][1][1], rp_[7]);
            }

            // Pointwise LSTM cell per (row, hp): pairs {f,g} and {i,o}
            float hv[2][2];
            #pragma unroll
            for (int row = 0; row < 2; row++) {
                #pragma unroll
                for (int hp = 0; hp < 2; hp++) {
                    float f, gg, ii, oo;
                    unpack2(acc[row][hp][0], f, gg);
                    unpack2(acc[row][hp][1], ii, oo);
                    float cn = carr[row][hp] * sigm(f) + tanh_(gg) * sigm(ii);
                    carr[row][hp] = cn;
                    hv[row][hp] = sigm(oo) * tanh_(cn);
                }
            }

            // publish h_new into this bslab's slice; stage out tile
            #pragma unroll
            for (int hp = 0; hp < 2; hp++) {
                int h = h0 + hq * 2 + hp;
                *(float2*)&g_h2[d][buf ^ 1][bslab][h][r0] =
                    make_float2(hv[0][hp], hv[1][hp]);
                ob[r0 * 16 + hq * 2 + hp] = hv[0][hp];
                ob[(r0 + 1) * 16 + hq * 2 + hp] = hv[1][hp];
            }
        }

        __syncthreads();                      // stores done, all reads done
        if (tid == 0) st_release(myflag, (unsigned)(t + 1));

        // coalesced out write (overlaps next spin): out[s][b][d*512+h0..+16)
        if (tid < 128) {
            int bl = tid >> 2, seg = (tid & 3) * 4;
            float4 v = *(float4*)&ob[bl * 16 + seg];
            *(float4*)&out[(size_t)s * (Bsz * 2 * Hsz)
                           + (size_t)(b0s + bl) * (2 * Hsz)
                           + d * Hsz + h0 + seg] = v;
        }
    }
}

// ---------------------------------------------------------------------------
__global__ void k_gather(const unsigned char* __restrict__ mask,
                         const float* __restrict__ out,
                         float* __restrict__ hf, float* __restrict__ hb)
{
    __shared__ int sred[256];
    __shared__ int smode;
    const int b = blockIdx.x, tid = threadIdx.x;

    if (tid == 0) {
        const int* ip = (const int*)mask;
        int bytemode = 0;
        for (int j = 0; j < 8; j++) {
            unsigned int v = (unsigned int)ip[j];
            if (v > 1u) bytemode = 1;
        }
        smode = bytemode;
    }
    __syncthreads();

    int v;
    if (smode) {
        v  = mask[b * Ssz + tid] ? 1 : 0;
        v += mask[b * Ssz + 256 + tid] ? 1 : 0;
    } else {
        const int* ip = (const int*)mask;
        v  = ip[b * Ssz + tid] ? 1 : 0;
        v += ip[b * Ssz + 256 + tid] ? 1 : 0;
    }
    sred[tid] = v;
    __syncthreads();
    for (int st = 128; st > 0; st >>= 1) {
        if (tid < st) sred[tid] += sred[tid + st];
        __syncthreads();
    }
    int len = sred[0];
    int idx = len > 0 ? len - 1 : 0;

    hf[b * Hsz + tid]       = out[(size_t)idx * 65536 + b * 1024 + tid];
    hf[b * Hsz + tid + 256] = out[(size_t)idx * 65536 + b * 1024 + tid + 256];
    hb[b * Hsz + tid]       = out[(size_t)b * 1024 + 512 + tid];
    hb[b * Hsz + tid + 256] = out[(size_t)b * 1024 + 512 + tid + 256];
}

// ---------------------------------------------------------------------------
extern "C" void kernel_launch(void* const* d_in, const int* in_sizes, int n_in,
                              void* d_out, int out_size)
{
    const float* x  = (const float*)d_in[0];
    const unsigned char* mask = (const unsigned char*)d_in[1];
    const float* Uf = (const float*)d_in[2];
    const float* Wf = (const float*)d_in[3];
    const float* bf = (const float*)d_in[4];
    const float* Ub = (const float*)d_in[5];
    const float* Wb = (const float*)d_in[6];
    const float* bb = (const float*)d_in[7];

    float* out = (float*)d_out;                       // [S][B][2H]
    float* hf  = out + (size_t)Ssz * Bsz * 2 * Hsz;   // [B][H]
    float* hb  = hf + (size_t)Bsz * Hsz;              // [B][H]

    k_init<<<512, 256>>>();
    k_u3<<<2048, 256>>>(Uf, Ub);

    dim3 gx(64, 512);
    k_xw<<<gx, 256>>>(x, Wf, Wb, bf, bb);

    cudaFuncSetAttribute(k_rec, cudaFuncAttributeMaxDynamicSharedMemorySize, SM_REC);
    k_rec<<<128, 512, SM_REC>>>(out);

    k_gather<<<64, 256>>>(mask, out, hf, hb);
}

// round 17
// speedup vs baseline: 1.3527x; 1.3527x over previous
#include <cuda_runtime.h>

#define Bsz 64
#define Ssz 512
#define Hsz 512
#define Isz 512

typedef unsigned long long u64;

// Scratch (allocation-free rule: __device__ globals)
__device__ float g_xw[134217728];          // [d][s][g][h][b] : 512MB
__device__ float g_h2[2][2][2][Hsz][32];   // [d][buf][bslab][k(=h)][b_l]
__device__ float g_U3[2][Hsz][Hsz][4];     // [d][k][h][g] undup'd, 8MB
__device__ unsigned g_flag[2][2][32];      // [d][bslab][hslab] step flags

__device__ __forceinline__ u64 packf2(float x, float y) {
    u64 r; asm("mov.b64 %0, {%1,%2};" : "=l"(r) : "f"(x), "f"(y)); return r;
}
__device__ __forceinline__ void unpack2(u64 v, float& x, float& y) {
    asm("mov.b64 {%0,%1}, %2;" : "=f"(x), "=f"(y) : "l"(v));
}
__device__ __forceinline__ void fma2(u64& d, u64 a, u64 b) {
    asm("fma.rn.f32x2 %0, %1, %2, %0;" : "+l"(d) : "l"(a), "l"(b));
}
__device__ __forceinline__ void add2(u64& d, u64 a) {
    asm("add.rn.f32x2 %0, %0, %1;" : "+l"(d) : "l"(a));
}
__device__ __forceinline__ float sigm(float x) {
    float e; asm("ex2.approx.f32 %0, %1;" : "=f"(e) : "f"(x * -1.4426950408889634f));
    float r; asm("rcp.approx.f32 %0, %1;" : "=f"(r) : "f"(1.0f + e));
    return r;
}
__device__ __forceinline__ float tanh_(float x) {
    float e; asm("ex2.approx.f32 %0, %1;" : "=f"(e) : "f"(x * 2.8853900817779268f));
    float r; asm("rcp.approx.f32 %0, %1;" : "=f"(r) : "f"(1.0f + e));
    return 1.0f - 2.0f * r;
}
__device__ __forceinline__ void st_release(unsigned* p, unsigned v) {
    asm volatile("st.release.gpu.global.u32 [%0], %1;" :: "l"(p), "r"(v) : "memory");
}
__device__ __forceinline__ unsigned ld_acquire(const unsigned* p) {
    unsigned v;
    asm volatile("ld.acquire.gpu.global.u32 %0, [%1];" : "=r"(v) : "l"(p) : "memory");
    return v;
}
__device__ __forceinline__ void mbar_init(unsigned mbar, unsigned count) {
    asm volatile("mbarrier.init.shared.b64 [%0], %1;" :: "r"(mbar), "r"(count) : "memory");
}
__device__ __forceinline__ void mbar_expect_tx(unsigned mbar, unsigned bytes) {
    asm volatile("mbarrier.arrive.expect_tx.shared.b64 _, [%0], %1;"
                 :: "r"(mbar), "r"(bytes) : "memory");
}
__device__ __forceinline__ void bulk_g2s(unsigned dst, const void* src,
                                         unsigned bytes, unsigned mbar) {
    asm volatile(
        "cp.async.bulk.shared::cluster.global.mbarrier::complete_tx::bytes "
        "[%0], [%1], %2, [%3];"
        :: "r"(dst), "l"(src), "r"(bytes), "r"(mbar) : "memory");
}
__device__ __forceinline__ void mbar_wait(unsigned mbar, unsigned parity) {
    unsigned done;
    do {
        asm volatile(
            "{\n\t.reg .pred p;\n\t"
            "mbarrier.try_wait.parity.acquire.cta.shared::cta.b64 p, [%1], %2;\n\t"
            "selp.b32 %0, 1, 0, p;\n\t}"
            : "=r"(done) : "r"(mbar), "r"(parity) : "memory");
    } while (!done);
}

// ---------------------------------------------------------------------------
__global__ void k_init() {
    int i = blockIdx.x * 256 + threadIdx.x;
    float* ph = &g_h2[0][0][0][0][0];
    if (i < 2 * 2 * 2 * Hsz * 32) ph[i] = 0.0f;
    if (i < 128) (&g_flag[0][0][0])[i] = 0u;
}

// Build g_U3[d][k][h][g] = U[d][g][k][h] (gates contiguous, undup'd).
__global__ void k_u3(const float* __restrict__ Uf, const float* __restrict__ Ub) {
    int i = blockIdx.x * 256 + threadIdx.x;       // over 2*512*512 (d,k,h)
    int d = i >> 18;
    int k = (i >> 9) & 511;
    int h = i & 511;
    const float* U = d ? Ub : Uf;
    float4 v;
    v.x = U[0 * 262144 + k * 512 + h];
    v.y = U[1 * 262144 + k * 512 + h];
    v.z = U[2 * 262144 + k * 512 + h];
    v.w = U[3 * 262144 + k * 512 + h];
    *(float4*)&g_U3[d][k][h][0] = v;
}

// ---------------------------------------------------------------------------
// Input projection: xw[d][s][g][h][b] = sum_i x[b][s][i] * W_d[g][i][h] + b_d[g][h]
// 128 threads, C tile 64(b) x 64(h). Thread: warp w -> cols [16w,16w+16),
// lane l: rows r0 = 4*(l&15), col base c0 = 16w + 8*(l>>4).
// Per k: 1 LDS.128 (A, 4 rows) + 2 LDS.128 (B) + 16 FFMA2.
__global__ __launch_bounds__(128) void k_xw(
    const float* __restrict__ x,
    const float* __restrict__ Wf, const float* __restrict__ Wb,
    const float* __restrict__ bf, const float* __restrict__ bb)
{
    __shared__ float As[32][68];   // As[k][row(b)]  (68: 16B-aligned rows)
    __shared__ float Bs[32][68];   // Bs[k][col(h)]

    const int tid = threadIdx.x;
    const int s = blockIdx.y;
    const int ct = blockIdx.x;             // 0..63
    const int d = ct >> 5;
    const int g = (ct >> 3) & 3;
    const int h0 = (ct & 7) * 64;

    const float* W = (d ? Wb : Wf) + (size_t)g * Hsz * Isz + h0;
    const float* bias = (d ? bb : bf) + g * Hsz + h0;

    // A staging: rows {ra, ra+32}, 8 k-floats at k4
    const int ra = tid >> 2, k4 = (tid & 3) * 8;
    // B staging: col c4*4, k rows {kb, kb+8, kb+16, kb+24}
    const int c4 = tid & 15, kb = tid >> 4;
    const float* xg = x + ((size_t)ra * Ssz + s) * Isz + k4;
    const size_t xrow2 = (size_t)32 * Ssz * Isz;

    const int l = tid & 31, w = tid >> 5;
    const int r0 = 4 * (l & 15);
    const int c0 = 16 * w + 8 * (l >> 4);

    u64 acc[4][4] = {};   // acc[row i][col pair j]

    float4 a00 = *(const float4*)(xg);
    float4 a01 = *(const float4*)(xg + 4);
    float4 a10 = *(const float4*)(xg + xrow2);
    float4 a11 = *(const float4*)(xg + xrow2 + 4);
    float4 rB[4];
    #pragma unroll
    for (int j = 0; j < 4; j++)
        rB[j] = *(const float4*)(W + (size_t)(kb + 8 * j) * Hsz + c4 * 4);

    for (int t = 0; t < 16; t++) {
        {
            As[k4 + 0][ra] = a00.x; As[k4 + 1][ra] = a00.y;
            As[k4 + 2][ra] = a00.z; As[k4 + 3][ra] = a00.w;
            As[k4 + 4][ra] = a01.x; As[k4 + 5][ra] = a01.y;
            As[k4 + 6][ra] = a01.z; As[k4 + 7][ra] = a01.w;
            As[k4 + 0][ra + 32] = a10.x; As[k4 + 1][ra + 32] = a10.y;
            As[k4 + 2][ra + 32] = a10.z; As[k4 + 3][ra + 32] = a10.w;
            As[k4 + 4][ra + 32] = a11.x; As[k4 + 5][ra + 32] = a11.y;
            As[k4 + 6][ra + 32] = a11.z; As[k4 + 7][ra + 32] = a11.w;
            #pragma unroll
            for (int j = 0; j < 4; j++)
                *(float4*)&Bs[kb + 8 * j][c4 * 4] = rB[j];
        }
        __syncthreads();
        if (t < 15) {
            int k0 = (t + 1) * 32;
            a00 = *(const float4*)(xg + k0);
            a01 = *(const float4*)(xg + k0 + 4);
            a10 = *(const float4*)(xg + xrow2 + k0);
            a11 = *(const float4*)(xg + xrow2 + k0 + 4);
            #pragma unroll
            for (int j = 0; j < 4; j++)
                rB[j] = *(const float4*)(W + (size_t)(k0 + kb + 8 * j) * Hsz + c4 * 4);
        }
        #pragma unroll
        for (int kk = 0; kk < 32; kk++) {
            float4 av = *(const float4*)&As[kk][r0];
            ulonglong2 b01 = *(const ulonglong2*)&Bs[kk][c0];
            ulonglong2 b23 = *(const ulonglong2*)&Bs[kk][c0 + 4];
            u64 a0 = packf2(av.x, av.x);
            u64 a1 = packf2(av.y, av.y);
            u64 a2 = packf2(av.z, av.z);
            u64 a3 = packf2(av.w, av.w);
            fma2(acc[0][0], a0, b01.x); fma2(acc[0][1], a0, b01.y);
            fma2(acc[0][2], a0, b23.x); fma2(acc[0][3], a0, b23.y);
            fma2(acc[1][0], a1, b01.x); fma2(acc[1][1], a1, b01.y);
            fma2(acc[1][2], a1, b23.x); fma2(acc[1][3], a1, b23.y);
            fma2(acc[2][0], a2, b01.x); fma2(acc[2][1], a2, b01.y);
            fma2(acc[2][2], a2, b23.x); fma2(acc[2][3], a2, b23.y);
            fma2(acc[3][0], a3, b01.x); fma2(acc[3][1], a3, b01.y);
            fma2(acc[3][2], a3, b23.x); fma2(acc[3][3], a3, b23.y);
        }
        __syncthreads();
    }

    // Epilogue: per col pair j, 2 cols; per col a float4 of 4 consecutive b.
    size_t gb = (((size_t)d * Ssz + s) * 4 + g) * (size_t)Hsz * Bsz;
    #pragma unroll
    for (int j = 0; j < 4; j++) {
        float2 bb2 = *(const float2*)&bias[c0 + 2 * j];
        float lo[4], hi[4];
        #pragma unroll
        for (int i = 0; i < 4; i++) unpack2(acc[i][j], lo[i], hi[i]);
        int hc = h0 + c0 + 2 * j;
        *(float4*)&g_xw[gb + (size_t)hc * Bsz + r0] =
            make_float4(lo[0] + bb2.x, lo[1] + bb2.x, lo[2] + bb2.x, lo[3] + bb2.x);
        *(float4*)&g_xw[gb + (size_t)(hc + 1) * Bsz + r0] =
            make_float4(hi[0] + bb2.y, hi[1] + bb2.y, hi[2] + bb2.y, hi[3] + bb2.y);
    }
}

// ---------------------------------------------------------------------------
// Persistent recurrence kernel (R14, proven): R12 GEMM on b-split partition.
// Grid 128: d = bx>>6; hslab = (bx&63)>>1 (h0 = 16*hslab); bslab = bx&1
// (b0s = 32*bslab). 512 threads, 1 block/SM, 4-way split-K (kq = tid>>7).
// Thread (t128): rp = t128>>3 (b rows 2rp, 2rp+1 of 32), hq = t128&7
// (h = h0 + 2hq, +1; all 4 gates; pairs {f,g},{i,o}).
// A = g_h2 slice [512][32] via two 32KB cp.async.bulk (2 mbarriers).
// B = [k][68-float row], col(hq) = hq*8 + (hq>>2)*4  -> conflict-free quads.
// Smem: mbar 32 | ob 2KB | red 24KB | B 136KB | A 64KB = 231,552 B
#define SM_MB   0
#define SM_OB   32
#define SM_RED  2080
#define SM_BS   26752
#define SM_AS   166016
#define SM_REC  231552

__global__ __launch_bounds__(512, 1) void k_rec(float* __restrict__ out)
{
    extern __shared__ char smraw[];
    float* ob  = (float*)(smraw + SM_OB);    // [32 b][16 h]
    u64*   red = (u64*)  (smraw + SM_RED);   // [3*128][8]
    float* Bsf = (float*)(smraw + SM_BS);    // [k][68]
    float* Ahs = (float*)(smraw + SM_AS);    // [k][32]

    const int tid = threadIdx.x;
    const int kq = tid >> 7;
    const int t128 = tid & 127;
    const int d = blockIdx.x >> 6;
    const int hslab = (blockIdx.x & 63) >> 1;
    const int bslab = blockIdx.x & 1;
    const int h0 = hslab * 16;
    const int b0s = bslab * 32;

    const unsigned smem_u32 = (unsigned)__cvta_generic_to_shared(smraw);
    const unsigned mb0 = smem_u32 + SM_MB;
    const unsigned mb1 = smem_u32 + SM_MB + 8;
    const unsigned ah_u32 = smem_u32 + SM_AS;

    if (tid == 0) { mbar_init(mb0, 1); mbar_init(mb1, 1); }

    // ---- load U slab once: local (hl,g) -> padded col hq*8+(hq>>2)*4+hp*4+g
    {
        const float* src = &g_U3[d][0][h0][0];
        for (int i = tid; i < 512 * 64; i += 512) {
            int k = i >> 6, j6 = i & 63;
            int hl = j6 >> 2, g = j6 & 3;
            int hqq = hl >> 1, hpp = hl & 1;
            int col = hqq * 8 + (hqq >> 2) * 4 + hpp * 4 + g;
            Bsf[k * 68 + col] = src[(size_t)k * 2048 + j6];
        }
    }

    const int rp = t128 >> 3;                // 0..15
    const int hq = t128 & 7;                 // 0..7
    const int r0 = rp * 2;
    const int bcol = hq * 8 + (hq >> 2) * 4;
    const int kbase = kq * 128;
    const unsigned mymb = (kq < 2) ? mb0 : mb1;

    unsigned* myflag = &g_flag[d][bslab][hslab];
    const unsigned* flags = &g_flag[d][bslab][0];

    const float* xwd = &g_xw[0] + (size_t)d * Ssz * 4 * Hsz * Bsz;

    float carr[2][2] = {{0.f, 0.f}, {0.f, 0.f}};   // c[row][hp]
    __syncthreads();   // U slab + mbarriers visible

    #pragma unroll 1
    for (int t = 0; t < Ssz; t++) {
        const int s = d ? (Ssz - 1 - t) : t;
        const int buf = t & 1;
        const unsigned parity = (unsigned)(t & 1);

        // seed acc (quarter 0) with xw — issued before wait, overlaps spin
        u64 acc[2][2][2] = {};
        if (kq == 0) {
            #pragma unroll
            for (int hp = 0; hp < 2; hp++) {
                int h = h0 + hq * 2 + hp;
                const float* xp = xwd + (size_t)s * 4 * Hsz * Bsz
                                + (size_t)h * Bsz + b0s + r0;
                float2 vf = *(const float2*)(xp);
                float2 vg = *(const float2*)(xp + (size_t)Hsz * Bsz);
                float2 vi = *(const float2*)(xp + (size_t)2 * Hsz * Bsz);
                float2 vo = *(const float2*)(xp + (size_t)3 * Hsz * Bsz);
                acc[0][hp][0] = packf2(vf.x, vg.x);
                acc[0][hp][1] = packf2(vi.x, vo.x);
                acc[1][hp][0] = packf2(vf.y, vg.y);
                acc[1][hp][1] = packf2(vi.y, vo.y);
            }
        }

        // wait: the 32 same-bslab writers finished step t-1
        if (t > 0) {
            if (tid < 32) {
                while (ld_acquire(flags + tid) < (unsigned)t) { }
            }
            __syncthreads();
        }

        // one 64KB slice as two 32KB bulk copies (k<256 / k>=256)
        if (tid == 0) {
            const float* hsrc = &g_h2[d][buf][bslab][0][0];
            mbar_expect_tx(mb0, 32768u);
            bulk_g2s(ah_u32, hsrc, 32768u, mb0);
            mbar_expect_tx(mb1, 32768u);
            bulk_g2s(ah_u32 + 32768u, hsrc + 8192, 32768u, mb1);
        }
        mbar_wait(mymb, parity);

        // sync-free GEMM over my 128 k
        #pragma unroll 1
        for (int tt = 0; tt < 8; tt++) {
            const float* Ak = Ahs + (size_t)(kbase + tt * 16) * 32 + r0;
            const float* Bt = Bsf + (size_t)(kbase + tt * 16) * 68 + bcol;
            #pragma unroll
            for (int kk = 0; kk < 16; kk++) {
                float2 a = *(const float2*)(Ak + kk * 32);
                u64 ax = packf2(a.x, a.x);
                u64 ay = packf2(a.y, a.y);
                ulonglong2 b0 = *(const ulonglong2*)(Bt + kk * 68);       // hp=0
                ulonglong2 b1 = *(const ulonglong2*)(Bt + kk * 68 + 4);   // hp=1
                fma2(acc[0][0][0], ax, b0.x);
                fma2(acc[0][0][1], ax, b0.y);
                fma2(acc[0][1][0], ax, b1.x);
                fma2(acc[0][1][1], ax, b1.y);
                fma2(acc[1][0][0], ay, b0.x);
                fma2(acc[1][0][1], ay, b0.y);
                fma2(acc[1][1][0], ay, b1.x);
                fma2(acc[1][1][1], ay, b1.y);
            }
        }

        // quarters 1..3 dump partials
        if (kq > 0) {
            u64* rp_ = red + ((size_t)(kq - 1) * 128 + t128) * 8;
            *(ulonglong2*)(rp_)     = make_ulonglong2(acc[0][0][0], acc[0][0][1]);
            *(ulonglong2*)(rp_ + 2) = make_ulonglong2(acc[0][1][0], acc[0][1][1]);
            *(ulonglong2*)(rp_ + 4) = make_ulonglong2(acc[1][0][0], acc[1][0][1]);
            *(ulonglong2*)(rp_ + 6) = make_ulonglong2(acc[1][1][0], acc[1][1][1]);
        }
        __syncthreads();

        if (kq == 0) {
            #pragma unroll
            for (int q = 0; q < 3; q++) {
                const u64* rp_ = red + ((size_t)q * 128 + t128) * 8;
                add2(acc[0][0][0], rp_[0]); add2(acc[0][0][1], rp_[1]);
                add2(acc[0][1][0], rp_[2]); add2(acc[0][1][1], rp_[3]);
                add2(acc[1][0][0], rp_[4]); add2(acc[1][0][1], rp_[5]);
                add2(acc[1][1][0], rp_[6]); add2(acc[1][1][1], rp_[7]);
            }

            // Pointwise LSTM cell per (row, hp): pairs {f,g} and {i,o}
            float hv[2][2];
            #pragma unroll
            for (int row = 0; row < 2; row++) {
                #pragma unroll
                for (int hp = 0; hp < 2; hp++) {
                    float f, gg, ii, oo;
                    unpack2(acc[row][hp][0], f, gg);
                    unpack2(acc[row][hp][1], ii, oo);
                    float cn = carr[row][hp] * sigm(f) + tanh_(gg) * sigm(ii);
                    carr[row][hp] = cn;
                    hv[row][hp] = sigm(oo) * tanh_(cn);
                }
            }

            // publish h_new into this bslab's slice; stage out tile
            #pragma unroll
            for (int hp = 0; hp < 2; hp++) {
                int h = h0 + hq * 2 + hp;
                *(float2*)&g_h2[d][buf ^ 1][bslab][h][r0] =
                    make_float2(hv[0][hp], hv[1][hp]);
                ob[r0 * 16 + hq * 2 + hp] = hv[0][hp];
                ob[(r0 + 1) * 16 + hq * 2 + hp] = hv[1][hp];
            }
        }

        __syncthreads();                      // stores done, all reads done
        if (tid == 0) st_release(myflag, (unsigned)(t + 1));

        // coalesced out write (overlaps next spin): out[s][b][d*512+h0..+16)
        if (tid < 128) {
            int bl = tid >> 2, seg = (tid & 3) * 4;
            float4 v = *(float4*)&ob[bl * 16 + seg];
            *(float4*)&out[(size_t)s * (Bsz * 2 * Hsz)
                           + (size_t)(b0s + bl) * (2 * Hsz)
                           + d * Hsz + h0 + seg] = v;
        }
    }
}

// ---------------------------------------------------------------------------
__global__ void k_gather(const unsigned char* __restrict__ mask,
                         const float* __restrict__ out,
                         float* __restrict__ hf, float* __restrict__ hb)
{
    __shared__ int sred[256];
    __shared__ int smode;
    const int b = blockIdx.x, tid = threadIdx.x;

    if (tid == 0) {
        const int* ip = (const int*)mask;
        int bytemode = 0;
        for (int j = 0; j < 8; j++) {
            unsigned int v = (unsigned int)ip[j];
            if (v > 1u) bytemode = 1;
        }
        smode = bytemode;
    }
    __syncthreads();

    int v;
    if (smode) {
        v  = mask[b * Ssz + tid] ? 1 : 0;
        v += mask[b * Ssz + 256 + tid] ? 1 : 0;
    } else {
        const int* ip = (const int*)mask;
        v  = ip[b * Ssz + tid] ? 1 : 0;
        v += ip[b * Ssz + 256 + tid] ? 1 : 0;
    }
    sred[tid] = v;
    __syncthreads();
    for (int st = 128; st > 0; st >>= 1) {
        if (tid < st) sred[tid] += sred[tid + st];
        __syncthreads();
    }
    int len = sred[0];
    int idx = len > 0 ? len - 1 : 0;

    hf[b * Hsz + tid]       = out[(size_t)idx * 65536 + b * 1024 + tid];
    hf[b * Hsz + tid + 256] = out[(size_t)idx * 65536 + b * 1024 + tid + 256];
    hb[b * Hsz + tid]       = out[(size_t)b * 1024 + 512 + tid];
    hb[b * Hsz + tid + 256] = out[(size_t)b * 1024 + 512 + tid + 256];
}

// ---------------------------------------------------------------------------
extern "C" void kernel_launch(void* const* d_in, const int* in_sizes, int n_in,
                              void* d_out, int out_size)
{
    const float* x  = (const float*)d_in[0];
    const unsigned char* mask = (const unsigned char*)d_in[1];
    const float* Uf = (const float*)d_in[2];
    const float* Wf = (const float*)d_in[3];
    const float* bf = (const float*)d_in[4];
    const float* Ub = (const float*)d_in[5];
    const float* Wb = (const float*)d_in[6];
    const float* bb = (const float*)d_in[7];

    float* out = (float*)d_out;                       // [S][B][2H]
    float* hf  = out + (size_t)Ssz * Bsz * 2 * Hsz;   // [B][H]
    float* hb  = hf + (size_t)Bsz * Hsz;              // [B][H]

    k_init<<<512, 256>>>();
    k_u3<<<2048, 256>>>(Uf, Ub);

    dim3 gx(64, 512);
    k_xw<<<gx, 128>>>(x, Wf, Wb, bf, bb);

    cudaFuncSetAttribute(k_rec, cudaFuncAttributeMaxDynamicSharedMemorySize, SM_REC);
    k_rec<<<128, 512, SM_REC>>>(out);

    k_gather<<<64, 256>>>(mask, out, hf, hb);
}